// round 2
// baseline (speedup 1.0000x reference)
#include <cuda_runtime.h>

#define BS   2048
#define SEQ  288
#define TST  288
#define HID  64
#define DSZ  29
#define G3   192
#define NTHR 512

typedef unsigned long long u64;

__device__ __forceinline__ u64 pk2(float x, float y) {
    u64 r; asm("mov.b64 %0,{%1,%2};" : "=l"(r) : "f"(x), "f"(y)); return r;
}
__device__ __forceinline__ void upk2(u64 v, float& x, float& y) {
    asm("mov.b64 {%0,%1},%2;" : "=f"(x), "=f"(y) : "l"(v));
}
__device__ __forceinline__ u64 ffma2(u64 a, u64 b, u64 c) {
    u64 d; asm("fma.rn.f32x2 %0,%1,%2,%3;" : "=l"(d) : "l"(a), "l"(b), "l"(c)); return d;
}
__device__ __forceinline__ u64 fadd2(u64 a, u64 b) {
    u64 d; asm("add.rn.f32x2 %0,%1,%2;" : "=l"(d) : "l"(a), "l"(b)); return d;
}

// shared memory layout (float offsets) — all even (u64-aligned), bases 16B-aligned
#define GX_OFF   0
#define GH_OFF   192
#define H_OFF    384
#define X_OFF    448     // double buffer 2 x 32
#define CTX_OFF  512
#define WK_OFF   576
#define BK_OFF   640
#define W28_OFF  648     // 192 floats: Wih[:,28] column
#define OUTS_OFF 840
#define WIH_OFF  844     // 192 rows x 30 floats (28 used, stride 30 keeps u64 align)
#define SMEM_FLOATS (WIH_OFF + 192 * 30)

__global__ __launch_bounds__(NTHR, 1)
void decoder_persist_kernel(const float* __restrict__ xdec,
                            const float* __restrict__ enc,
                            const float* __restrict__ hid,
                            const float* __restrict__ Wih,
                            const float* __restrict__ Whh,
                            const float* __restrict__ bih,
                            const float* __restrict__ bhh,
                            const float* __restrict__ Wk,
                            const float* __restrict__ bk,
                            const float* __restrict__ W1,
                            const float* __restrict__ b1,
                            const float* __restrict__ W2,
                            const float* __restrict__ b2,
                            float* __restrict__ out)
{
    __shared__ float sm[SMEM_FLOATS];
    const int tid  = threadIdx.x;
    const int warp = tid >> 5;
    const int lane = tid & 31;
    const int b    = blockIdx.x;
    const unsigned FULL = 0xffffffffu;

    // ---- union register array: GRU->Whh row (32), MLP->W1 row (32), ATT->val (36)
    u64 wreg[36];
    float ba = 0.f, bb = 0.f, b2r = 0.f;

    if (tid < G3) {
        const ulonglong2* wp = reinterpret_cast<const ulonglong2*>(Whh + tid * HID);
#pragma unroll
        for (int k = 0; k < 16; ++k) { ulonglong2 v = wp[k]; wreg[2*k] = v.x; wreg[2*k+1] = v.y; }
        ba = bih[tid]; bb = bhh[tid];
    } else if (warp == 6) {
        const ulonglong2* wp = reinterpret_cast<const ulonglong2*>(W1 + lane * HID);
#pragma unroll
        for (int k = 0; k < 16; ++k) { ulonglong2 v = wp[k]; wreg[2*k] = v.x; wreg[2*k+1] = v.y; }
        ba = b1[lane]; bb = W2[lane]; b2r = b2[0];
    } else if (warp >= 8) {
        const int head = warp - 8;
#pragma unroll
        for (int i = 0; i < 9; ++i) {
            int s = lane + (i << 5);
            const ulonglong2* vp = reinterpret_cast<const ulonglong2*>(
                enc + ((size_t)s * BS + b) * HID + head * 8);
            ulonglong2 v0 = vp[0], v1 = vp[1];
            wreg[4*i+0] = v0.x; wreg[4*i+1] = v0.y;
            wreg[4*i+2] = v1.x; wreg[4*i+3] = v1.y;
        }
    }

    // ---- SMEM init (all threads cooperate)
    for (int idx = tid; idx < G3 * DSZ; idx += NTHR) {
        int row = idx / DSZ, k = idx - row * DSZ;
        float v = Wih[idx];
        if (k < 28) sm[WIH_OFF + row * 30 + k] = v;
        else        sm[W28_OFF + row] = v;
    }
    if (tid < HID) sm[H_OFF + tid] = hid[(size_t)b * HID + tid];
    if (tid < 28)  sm[X_OFF + tid] = xdec[(size_t)b * (TST + 1) * DSZ + tid];
    if (tid < 64)  sm[WK_OFF + tid] = Wk[tid];
    if (tid < 8)   sm[BK_OFF + tid] = bk[tid];
    if (tid == 0)  sm[OUTS_OFF] = xdec[(size_t)b * (TST + 1) * DSZ + 28];

    float xv_pre = 0.f;
    if (warp == 7 && lane < 28)
        xv_pre = xdec[((size_t)b * (TST + 1) + 1) * DSZ + lane];

    __syncthreads();

    for (int t = 0; t < TST; ++t) {
        const int cur = t & 1, nxt = cur ^ 1;

        // ================= PHASE A =================
        if (tid < G3) {
            u64 ax = pk2(ba, 0.f);
            u64 ah = pk2(bb, 0.f);
            const u64* xp = reinterpret_cast<const u64*>(&sm[X_OFF + cur * 32]);
            const u64* wp = reinterpret_cast<const u64*>(&sm[WIH_OFF + tid * 30]);
#pragma unroll
            for (int k = 0; k < 14; ++k) ax = ffma2(wp[k], xp[k], ax);
            const ulonglong2* hp = reinterpret_cast<const ulonglong2*>(&sm[H_OFF]);
#pragma unroll
            for (int k = 0; k < 16; ++k) {
                ulonglong2 h2 = hp[k];
                ah = ffma2(wreg[2*k],   h2.x, ah);
                ah = ffma2(wreg[2*k+1], h2.y, ah);
            }
            float a0, a1, c0, c1;
            upk2(ax, a0, a1); upk2(ah, c0, c1);
            sm[GX_OFF + tid] = a0 + a1;
            sm[GH_OFF + tid] = c0 + c1;
        } else if (warp == 6) {
            if (t > 0) {  // output MLP for step t-1
                u64 acc = pk2(ba, 0.f);
                const ulonglong2* cp = reinterpret_cast<const ulonglong2*>(&sm[CTX_OFF]);
#pragma unroll
                for (int k = 0; k < 16; ++k) {
                    ulonglong2 c2 = cp[k];
                    acc = ffma2(wreg[2*k],   c2.x, acc);
                    acc = ffma2(wreg[2*k+1], c2.y, acc);
                }
                float y0, y1; upk2(acc, y0, y1);
                float p = fmaxf(y0 + y1, 0.f) * bb;
#pragma unroll
                for (int off = 16; off >= 1; off >>= 1)
                    p += __shfl_xor_sync(FULL, p, off);
                if (lane == 0) {
                    float o = p + b2r;
                    out[(size_t)b * TST + (t - 1)] = o;
                    sm[OUTS_OFF] = o;
                }
            }
        } else if (warp == 7) {  // x prefetch
            if (lane < 28) {
                sm[X_OFF + nxt * 32 + lane] = xv_pre;
                int row = (t + 2 <= TST) ? (t + 2) : TST;
                xv_pre = xdec[((size_t)b * (TST + 1) + row) * DSZ + lane];
            }
        }
        __syncthreads();

        // ================= PHASE C: gates + attention (warps 8..15, warp = head)
        if (warp >= 8) {
            const int head = warp - 8;

            float hn = 0.f;
            if (lane < 8) {
                const int i = head * 8 + lane;
                float o   = sm[OUTS_OFF];
                float gr  = sm[GX_OFF + i]        + sm[W28_OFF + i] * o        + sm[GH_OFF + i];
                float gz  = sm[GX_OFF + 64 + i]   + sm[W28_OFF + 64 + i] * o   + sm[GH_OFF + 64 + i];
                float gn  = sm[GX_OFF + 128 + i]  + sm[W28_OFF + 128 + i] * o;
                float ghn = sm[GH_OFF + 128 + i];
                float r  = 1.f / (1.f + __expf(-gr));
                float z  = 1.f / (1.f + __expf(-gz));
                float a  = gn + r * ghn;
                float e2 = __expf(2.f * a);
                float nt = 1.f - 2.f / (e2 + 1.f);
                float hp0 = sm[H_OFF + i];
                hn = nt + z * (hp0 - nt);
                sm[H_OFF + i] = hn;            // for next step's GRU
            }

            // q' = h_new @ Wk (lane e<8), qb = h_new . bk (lane 8)
            float q = 0.f;
#pragma unroll
            for (int d = 0; d < 8; ++d) {
                float hv = __shfl_sync(FULL, hn, d);
                float w  = (lane < 8) ? sm[WK_OFF + d * 8 + lane]
                         : ((lane == 8) ? sm[BK_OFF + d] : 0.f);
                q = fmaf(hv, w, q);
            }
            u64 qp2[4];
#pragma unroll
            for (int j = 0; j < 4; ++j)
                qp2[j] = pk2(__shfl_sync(FULL, q, 2 * j), __shfl_sync(FULL, q, 2 * j + 1));
            float qb = __shfl_sync(FULL, q, 8);

            // single-pass attention over register-resident val
            float wsum = 0.f;
            u64 c2[4] = {0ull, 0ull, 0ull, 0ull};
#pragma unroll
            for (int i = 0; i < 9; ++i) {
                u64 v0 = wreg[4*i+0], v1 = wreg[4*i+1], v2 = wreg[4*i+2], v3 = wreg[4*i+3];
                u64 acc = ffma2(qp2[0], v0, 0ull);
                acc = ffma2(qp2[1], v1, acc);
                acc = ffma2(qp2[2], v2, acc);
                acc = ffma2(qp2[3], v3, acc);
                float s0, s1; upk2(acc, s0, s1);
                float e = __expf(s0 + s1 + qb);   // scores bounded, safe w/o max-sub
                wsum += e;
                u64 ee = pk2(e, e);
                c2[0] = ffma2(ee, v0, c2[0]);
                c2[1] = ffma2(ee, v1, c2[1]);
                c2[2] = ffma2(ee, v2, c2[2]);
                c2[3] = ffma2(ee, v3, c2[3]);
            }
#pragma unroll
            for (int off = 16; off >= 1; off >>= 1) {
                wsum += __shfl_xor_sync(FULL, wsum, off);
#pragma unroll
                for (int j = 0; j < 4; ++j)
                    c2[j] = fadd2(c2[j], __shfl_xor_sync(FULL, c2[j], off));
            }
            if (lane == 0) {
                float inv = 1.f / wsum;
#pragma unroll
                for (int j = 0; j < 4; ++j) {
                    float d0, d1; upk2(c2[j], d0, d1);
                    sm[CTX_OFF + head * 8 + 2 * j]     = d0 * inv;
                    sm[CTX_OFF + head * 8 + 2 * j + 1] = d1 * inv;
                }
            }
        }
        __syncthreads();
    }

    // final output MLP for step TST-1
    if (warp == 6) {
        u64 acc = pk2(ba, 0.f);
        const ulonglong2* cp = reinterpret_cast<const ulonglong2*>(&sm[CTX_OFF]);
#pragma unroll
        for (int k = 0; k < 16; ++k) {
            ulonglong2 c2 = cp[k];
            acc = ffma2(wreg[2*k],   c2.x, acc);
            acc = ffma2(wreg[2*k+1], c2.y, acc);
        }
        float y0, y1; upk2(acc, y0, y1);
        float p = fmaxf(y0 + y1, 0.f) * bb;
#pragma unroll
        for (int off = 16; off >= 1; off >>= 1)
            p += __shfl_xor_sync(FULL, p, off);
        if (lane == 0)
            out[(size_t)b * TST + (TST - 1)] = p + b2r;
    }
}

extern "C" void kernel_launch(void* const* d_in, const int* in_sizes, int n_in,
                              void* d_out, int out_size)
{
    const float* xdec = (const float*)d_in[0];
    const float* enc  = (const float*)d_in[1];
    const float* hidp = (const float*)d_in[2];
    const float* Wih  = (const float*)d_in[3];
    const float* Whh  = (const float*)d_in[4];
    const float* bih  = (const float*)d_in[5];
    const float* bhh  = (const float*)d_in[6];
    const float* Wk   = (const float*)d_in[7];
    const float* bk   = (const float*)d_in[8];
    const float* W1   = (const float*)d_in[9];
    const float* b1   = (const float*)d_in[10];
    const float* W2   = (const float*)d_in[11];
    const float* b2   = (const float*)d_in[12];
    float* out = (float*)d_out;

    decoder_persist_kernel<<<BS, NTHR>>>(xdec, enc, hidp, Wih, Whh, bih, bhh,
                                         Wk, bk, W1, b1, W2, b2, out);
}

// round 3
// speedup vs baseline: 1.0421x; 1.0421x over previous
#include <cuda_runtime.h>

#define BS   2048
#define SEQ  288
#define TST  288
#define HID  64
#define DSZ  29
#define G3   192
#define NTHR 256

typedef unsigned long long u64;

__device__ __forceinline__ u64 pk2(float x, float y) {
    u64 r; asm("mov.b64 %0,{%1,%2};" : "=l"(r) : "f"(x), "f"(y)); return r;
}
__device__ __forceinline__ void upk2(u64 v, float& x, float& y) {
    asm("mov.b64 {%0,%1},%2;" : "=f"(x), "=f"(y) : "l"(v));
}
__device__ __forceinline__ u64 ffma2(u64 a, u64 b, u64 c) {
    u64 d; asm("fma.rn.f32x2 %0,%1,%2,%3;" : "=l"(d) : "l"(a), "l"(b), "l"(c)); return d;
}
__device__ __forceinline__ u64 fadd2(u64 a, u64 b) {
    u64 d; asm("add.rn.f32x2 %0,%1,%2;" : "=l"(d) : "l"(a), "l"(b)); return d;
}

// SMEM layout (float offsets); all bases 16B-aligned
#define GX_OFF   0
#define GH_OFF   192
#define H_OFF    384
#define X_OFF    448     // double buffer 2 x 32
#define CTX_OFF  512
#define WK_OFF   576
#define BK_OFF   640
#define W28_OFF  648     // Wih[:,28] column (192)
#define OUTS_OFF 840
#define SMEM_FLOATS 844

__global__ __launch_bounds__(NTHR, 1)
void decoder_persist_kernel(const float* __restrict__ xdec,
                            const float* __restrict__ enc,
                            const float* __restrict__ hid,
                            const float* __restrict__ Wih,
                            const float* __restrict__ Whh,
                            const float* __restrict__ bih,
                            const float* __restrict__ bhh,
                            const float* __restrict__ Wk,
                            const float* __restrict__ bk,
                            const float* __restrict__ W1,
                            const float* __restrict__ b1,
                            const float* __restrict__ W2,
                            const float* __restrict__ b2,
                            float* __restrict__ out)
{
    __shared__ float sm[SMEM_FLOATS];
    const int tid  = threadIdx.x;
    const int warp = tid >> 5;
    const int lane = tid & 31;
    const int b    = blockIdx.x;
    const unsigned FULL = 0xffffffffu;

    // ureg: Whh row (warps 0-5) / W1 row (warp 6)  -- explicit union
    u64 ureg[32];
    u64 wih[14];     // Wih row cols 0..27 (warps 0-5 only)
    u64 val[36];     // attention values, head = warp (all warps)
    float ba = 0.f, bb = 0.f, b2r = 0.f;

    if (tid < G3) {
        const ulonglong2* wp = reinterpret_cast<const ulonglong2*>(Whh + tid * HID);
#pragma unroll
        for (int k = 0; k < 16; ++k) { ulonglong2 v = wp[k]; ureg[2*k] = v.x; ureg[2*k+1] = v.y; }
        const float* wr = Wih + tid * DSZ;
#pragma unroll
        for (int k = 0; k < 14; ++k) wih[k] = pk2(wr[2*k], wr[2*k+1]);
        ba = bih[tid]; bb = bhh[tid];
    } else if (warp == 6) {
        const ulonglong2* wp = reinterpret_cast<const ulonglong2*>(W1 + lane * HID);
#pragma unroll
        for (int k = 0; k < 16; ++k) { ulonglong2 v = wp[k]; ureg[2*k] = v.x; ureg[2*k+1] = v.y; }
        ba = b1[lane]; bb = W2[lane]; b2r = b2[0];
    }

    // val[s][*] for this head into registers
#pragma unroll
    for (int i = 0; i < 9; ++i) {
        int s = lane + (i << 5);
        const ulonglong2* vp = reinterpret_cast<const ulonglong2*>(
            enc + ((size_t)s * BS + b) * HID + warp * 8);
        ulonglong2 v0 = vp[0], v1 = vp[1];
        val[4*i+0] = v0.x; val[4*i+1] = v0.y; val[4*i+2] = v1.x; val[4*i+3] = v1.y;
    }

    // SMEM init
    if (tid < HID) sm[H_OFF + tid] = hid[(size_t)b * HID + tid];
    if (tid < 28)  sm[X_OFF + tid] = xdec[(size_t)b * (TST + 1) * DSZ + tid];
    if (tid < 64)  sm[WK_OFF + tid] = Wk[tid];
    if (tid < 8)   sm[BK_OFF + tid] = bk[tid];
    if (tid < G3)  sm[W28_OFF + tid] = Wih[tid * DSZ + 28];
    if (tid == 0)  sm[OUTS_OFF] = xdec[(size_t)b * (TST + 1) * DSZ + 28];

    float xv_pre = 0.f;
    if (warp == 7 && lane < 28)
        xv_pre = xdec[((size_t)b * (TST + 1) + 1) * DSZ + lane];

    __syncthreads();

#pragma unroll 1
    for (int t = 0; t < TST; ++t) {
        const int cur = t & 1, nxt = cur ^ 1;

        // ===== PHASE A: GRU dots (w0-5) | MLP t-1 (w6) | x prefetch (w7) =====
        if (tid < G3) {
            u64 ax0 = pk2(ba, 0.f), ax1 = 0ull;
            const u64* xp = reinterpret_cast<const u64*>(&sm[X_OFF + cur * 32]);
#pragma unroll
            for (int k = 0; k < 14; k += 2) {
                ax0 = ffma2(wih[k],   xp[k],   ax0);
                ax1 = ffma2(wih[k+1], xp[k+1], ax1);
            }
            u64 ah0 = pk2(bb, 0.f), ah1 = 0ull, ah2 = 0ull, ah3 = 0ull;
            const ulonglong2* hp = reinterpret_cast<const ulonglong2*>(&sm[H_OFF]);
#pragma unroll
            for (int k = 0; k < 16; k += 2) {
                ulonglong2 ha = hp[k], hb2 = hp[k+1];
                ah0 = ffma2(ureg[2*k],   ha.x,  ah0);
                ah1 = ffma2(ureg[2*k+1], ha.y,  ah1);
                ah2 = ffma2(ureg[2*k+2], hb2.x, ah2);
                ah3 = ffma2(ureg[2*k+3], hb2.y, ah3);
            }
            u64 axs = fadd2(ax0, ax1);
            u64 ahs = fadd2(fadd2(ah0, ah1), fadd2(ah2, ah3));
            float a0, a1, c0, c1;
            upk2(axs, a0, a1); upk2(ahs, c0, c1);
            sm[GX_OFF + tid] = a0 + a1;
            sm[GH_OFF + tid] = c0 + c1;
        } else if (warp == 6) {
            if (t > 0) {
                u64 a0 = pk2(ba, 0.f), a1 = 0ull;
                const ulonglong2* cp = reinterpret_cast<const ulonglong2*>(&sm[CTX_OFF]);
#pragma unroll
                for (int k = 0; k < 16; ++k) {
                    ulonglong2 c2v = cp[k];
                    a0 = ffma2(ureg[2*k],   c2v.x, a0);
                    a1 = ffma2(ureg[2*k+1], c2v.y, a1);
                }
                float y0, y1, y2, y3;
                upk2(a0, y0, y1); upk2(a1, y2, y3);
                float p = fmaxf(y0 + y1 + y2 + y3, 0.f) * bb;
#pragma unroll
                for (int off = 16; off >= 1; off >>= 1)
                    p += __shfl_xor_sync(FULL, p, off);
                if (lane == 0) {
                    float o = p + b2r;
                    out[(size_t)b * TST + (t - 1)] = o;
                    sm[OUTS_OFF] = o;
                }
            }
        } else if (warp == 7) {
            if (lane < 28) {
                sm[X_OFF + nxt * 32 + lane] = xv_pre;
                int row = (t + 2 <= TST) ? (t + 2) : TST;
                xv_pre = xdec[((size_t)b * (TST + 1) + row) * DSZ + lane];
            }
        }
        __syncthreads();

        // ===== PHASE C: gates (lanes<8) + attention (all warps, head = warp) =====
        {
            const int head = warp;
            float hn = 0.f;
            if (lane < 8) {
                const int i = head * 8 + lane;
                float o   = sm[OUTS_OFF];
                float gr  = sm[GX_OFF + i]       + sm[W28_OFF + i] * o       + sm[GH_OFF + i];
                float gz  = sm[GX_OFF + 64 + i]  + sm[W28_OFF + 64 + i] * o  + sm[GH_OFF + 64 + i];
                float gn  = sm[GX_OFF + 128 + i] + sm[W28_OFF + 128 + i] * o;
                float ghn = sm[GH_OFF + 128 + i];
                float r  = 1.f / (1.f + __expf(-gr));
                float z  = 1.f / (1.f + __expf(-gz));
                float a  = gn + r * ghn;
                float e2 = __expf(2.f * a);
                float nt = 1.f - 2.f / (e2 + 1.f);
                float hp0 = sm[H_OFF + i];
                hn = nt + z * (hp0 - nt);
                sm[H_OFF + i] = hn;
            }

            float q = 0.f;
#pragma unroll
            for (int d = 0; d < 8; ++d) {
                float hv = __shfl_sync(FULL, hn, d);
                float w  = (lane < 8) ? sm[WK_OFF + d * 8 + lane]
                         : ((lane == 8) ? sm[BK_OFF + d] : 0.f);
                q = fmaf(hv, w, q);
            }
            u64 qp2[4];
#pragma unroll
            for (int j = 0; j < 4; ++j)
                qp2[j] = pk2(__shfl_sync(FULL, q, 2 * j), __shfl_sync(FULL, q, 2 * j + 1));
            float qb = __shfl_sync(FULL, q, 8);

            float w0 = 0.f, w1 = 0.f;
            u64 c2[4] = {0ull, 0ull, 0ull, 0ull};
#pragma unroll
            for (int i = 0; i < 9; ++i) {
                u64 v0 = val[4*i+0], v1 = val[4*i+1], v2 = val[4*i+2], v3 = val[4*i+3];
                u64 acc = ffma2(qp2[0], v0, 0ull);
                acc = ffma2(qp2[1], v1, acc);
                acc = ffma2(qp2[2], v2, acc);
                acc = ffma2(qp2[3], v3, acc);
                float s0, s1; upk2(acc, s0, s1);
                float e = __expf(s0 + s1 + qb);
                if (i & 1) w1 += e; else w0 += e;
                u64 ee = pk2(e, e);
                c2[0] = ffma2(ee, v0, c2[0]);
                c2[1] = ffma2(ee, v1, c2[1]);
                c2[2] = ffma2(ee, v2, c2[2]);
                c2[3] = ffma2(ee, v3, c2[3]);
            }
            float wsum = w0 + w1;
#pragma unroll
            for (int off = 16; off >= 1; off >>= 1) {
                wsum += __shfl_xor_sync(FULL, wsum, off);
#pragma unroll
                for (int j = 0; j < 4; ++j)
                    c2[j] = fadd2(c2[j], __shfl_xor_sync(FULL, c2[j], off));
            }
            if (lane == 0) {
                float inv = 1.f / wsum;
#pragma unroll
                for (int j = 0; j < 4; ++j) {
                    float d0, d1; upk2(c2[j], d0, d1);
                    sm[CTX_OFF + head * 8 + 2 * j]     = d0 * inv;
                    sm[CTX_OFF + head * 8 + 2 * j + 1] = d1 * inv;
                }
            }
        }
        __syncthreads();
    }

    // final output MLP (step TST-1)
    if (warp == 6) {
        u64 a0 = pk2(ba, 0.f), a1 = 0ull;
        const ulonglong2* cp = reinterpret_cast<const ulonglong2*>(&sm[CTX_OFF]);
#pragma unroll
        for (int k = 0; k < 16; ++k) {
            ulonglong2 c2v = cp[k];
            a0 = ffma2(ureg[2*k],   c2v.x, a0);
            a1 = ffma2(ureg[2*k+1], c2v.y, a1);
        }
        float y0, y1, y2, y3;
        upk2(a0, y0, y1); upk2(a1, y2, y3);
        float p = fmaxf(y0 + y1 + y2 + y3, 0.f) * bb;
#pragma unroll
        for (int off = 16; off >= 1; off >>= 1)
            p += __shfl_xor_sync(FULL, p, off);
        if (lane == 0)
            out[(size_t)b * TST + (TST - 1)] = p + b2r;
    }
}

extern "C" void kernel_launch(void* const* d_in, const int* in_sizes, int n_in,
                              void* d_out, int out_size)
{
    const float* xdec = (const float*)d_in[0];
    const float* enc  = (const float*)d_in[1];
    const float* hidp = (const float*)d_in[2];
    const float* Wih  = (const float*)d_in[3];
    const float* Whh  = (const float*)d_in[4];
    const float* bih  = (const float*)d_in[5];
    const float* bhh  = (const float*)d_in[6];
    const float* Wk   = (const float*)d_in[7];
    const float* bk   = (const float*)d_in[8];
    const float* W1   = (const float*)d_in[9];
    const float* b1   = (const float*)d_in[10];
    const float* W2   = (const float*)d_in[11];
    const float* b2   = (const float*)d_in[12];
    float* out = (float*)d_out;

    decoder_persist_kernel<<<BS, NTHR>>>(xdec, enc, hidp, Wih, Whh, bih, bhh,
                                         Wk, bk, W1, b1, W2, b2, out);
}